// round 1
// baseline (speedup 1.0000x reference)
#include <cuda_runtime.h>
#include <math.h>

// ---------------- problem constants ----------------
#define NBATCH 1024
#define TSRC   32
#define TOUT   64
#define NJ     24      // joints
#define NH     24      // hidden
#define KC     96      // 4 gates * 24
#define NT     192     // threads per block (8 j-tiles * 24 k-tiles)
#define WARM   24

// staging buffer for decode outputs o: [N, T, J*H]
__device__ float g_O[(size_t)NBATCH * TOUT * (NJ * NH)];

// SMPL tree adjacency incl. self-loop (precomputed from SMPL_PARENTS)
__constant__ int c_nbr[24][5] = {
    {0,1,2,3,-1},{1,0,4,-1,-1},{2,0,5,-1,-1},{3,0,6,-1,-1},
    {4,1,7,-1,-1},{5,2,8,-1,-1},{6,3,9,-1,-1},{7,4,10,-1,-1},
    {8,5,11,-1,-1},{9,6,12,13,14},{10,7,-1,-1,-1},{11,8,-1,-1,-1},
    {12,9,15,-1,-1},{13,9,16,-1,-1},{14,9,17,-1,-1},{15,12,-1,-1,-1},
    {16,13,18,-1,-1},{17,14,19,-1,-1},{18,16,20,-1,-1},{19,17,21,-1,-1},
    {20,18,22,-1,-1},{21,19,23,-1,-1},{22,20,-1,-1,-1},{23,21,-1,-1,-1}};
__constant__ int c_cnt[24] = {4,3,3,3, 3,3,3,3, 3,5,2,2, 3,3,3,2, 3,3,3,3, 3,3,2,2};
__constant__ float c_inv[24] = {
    1.f/4,1.f/3,1.f/3,1.f/3, 1.f/3,1.f/3,1.f/3,1.f/3,
    1.f/3,1.f/5,1.f/2,1.f/2, 1.f/3,1.f/3,1.f/3,1.f/2,
    1.f/3,1.f/3,1.f/3,1.f/3, 1.f/3,1.f/3,1.f/2,1.f/2};

// overflow-safe fast sigmoid / tanh (exp argument always <= 0)
__device__ __forceinline__ float sigm_f(float x) {
    float e = __expf(-fabsf(x));              // in (0,1]
    float r = __fdividef(1.f, 1.f + e);       // sigmoid(|x|)
    return x >= 0.f ? r : 1.f - r;
}
__device__ __forceinline__ float tanh_f(float x) {
    float e = __expf(-2.f * fabsf(x));        // in (0,1]
    float r = __fdividef(1.f - e, 1.f + e);   // tanh(|x|)
    return copysignf(r, x);
}

#define ACCROW(A, U_) \
    A.x = fmaf(U_.x,w0.x, fmaf(U_.y,w1.x, fmaf(U_.z,w2.x, fmaf(U_.w,w3.x, A.x)))); \
    A.y = fmaf(U_.x,w0.y, fmaf(U_.y,w1.y, fmaf(U_.z,w2.y, fmaf(U_.w,w3.y, A.y)))); \
    A.z = fmaf(U_.x,w0.z, fmaf(U_.y,w1.z, fmaf(U_.z,w2.z, fmaf(U_.w,w3.z, A.z)))); \
    A.w = fmaf(U_.x,w0.w, fmaf(U_.y,w1.w, fmaf(U_.z,w2.w, fmaf(U_.w,w3.w, A.w))));

// SMEM layout (floats):
//   Wt  [96][96]   transposed combined weights: Wt[i][g*24+k]
//   U   [24][96]   per-joint vector u = [aX | X | aH | h]
//   S   [24][96]   gate pre-activations
//   btot[96]       sage_x_b + sage_h_b + gate_b
//   gwm [72]       peepholes (i,f,o)
#define SM_WT 0
#define SM_U  (SM_WT + 96*96)
#define SM_S  (SM_U + 24*96)
#define SM_B  (SM_S + 24*96)
#define SM_GW (SM_B + 96)
#define SM1_FLOATS (SM_GW + 72)

__global__ void __launch_bounds__(NT, 4)
rec_kernel(const float* __restrict__ src, const float* __restrict__ tgt,
           const float* __restrict__ encW, const float* __restrict__ encB,
           const float* __restrict__ xWl, const float* __restrict__ xWr,
           const float* __restrict__ xb,
           const float* __restrict__ hWl, const float* __restrict__ hWr,
           const float* __restrict__ hb,
           const float* __restrict__ gw, const float* __restrict__ gb)
{
    extern __shared__ float sm[];
    float* Wt   = sm + SM_WT;
    float* U    = sm + SM_U;
    float* S    = sm + SM_S;
    float* btot = sm + SM_B;
    float* gwm  = sm + SM_GW;

    const int tid = threadIdx.x;
    const int n   = blockIdx.x;

    // ---- stage transposed combined weights: Wt[i][kc], kc = g*24+k ----
    // i: [0,24)=aX->xWl, [24,48)=X->xWr, [48,72)=aH->hWl, [72,96)=h->hWr
    for (int e = tid; e < 96*96; e += NT) {
        int i = e / 96, kc = e % 96;
        int g = kc / 24, k = kc % 24;
        float v;
        if      (i < 24) v = xWl[g*576 + k*24 + i];
        else if (i < 48) v = xWr[g*576 + k*24 + (i-24)];
        else if (i < 72) v = hWl[g*576 + k*24 + (i-48)];
        else             v = hWr[g*576 + k*24 + (i-72)];
        Wt[e] = v;
    }
    for (int e = tid; e < 96; e += NT) btot[e] = xb[e] + hb[e] + gb[e];
    for (int e = tid; e < 72; e += NT) gwm[e] = gw[e];

    // ---- init: X = relu(enc(src[n, TSRC-WARM])), h = 0, c = 0 ----
    #pragma unroll
    for (int r = 0; r < 3; r++) {
        int idx = tid + r*NT; int j = idx/24, h = idx%24;
        const float* x = src + (size_t)n*(TSRC*72) + (TSRC-WARM)*72 + j*3;
        float v = encB[h] + x[0]*encW[h*3+0] + x[1]*encW[h*3+1] + x[2]*encW[h*3+2];
        U[j*96 + 24 + h] = fmaxf(v, 0.f);
        U[j*96 + 72 + h] = 0.f;
    }
    float creg[3] = {0.f, 0.f, 0.f};   // cell state, owned per elementwise task
    __syncthreads();

    const int jt = tid / 24;           // j-tile: rows jt*3 .. jt*3+2
    const int kt = tid % 24;           // k-tile: cols kt*4 .. kt*4+3
    const float4* W4 = (const float4*)Wt;
    const float*  Uj = U + jt*3*96;

    for (int t = 0; t < WARM + TOUT; t++) {
        // ---- mean neighbor aggregation: aX <- X, aH <- h ----
        #pragma unroll
        for (int r = 0; r < 6; r++) {
            int task = tid + r*NT;
            int typ = task / 576;               // 0: aX, 1: aH
            int rem = task - typ*576;
            int j = rem/24, h = rem%24;
            int so = typ ? 72 : 24, dof = typ ? 48 : 0;
            float s = 0.f;
            int cnt = c_cnt[j];
            #pragma unroll
            for (int m = 0; m < 5; m++)
                if (m < cnt) s += U[c_nbr[j][m]*96 + so + h];
            U[j*96 + dof + h] = s * c_inv[j];
        }
        __syncthreads();

        // ---- fused matvec: S[j][kc] = btot[kc] + sum_i Wt[i][kc]*u[j][i] ----
        float4 bq = *(const float4*)(btot + kt*4);
        float4 a0 = bq, a1 = bq, a2 = bq;
        #pragma unroll 8
        for (int iq = 0; iq < 24; iq++) {
            float4 ua = ((const float4*)(Uj      ))[iq];
            float4 ub = ((const float4*)(Uj +  96))[iq];
            float4 uc = ((const float4*)(Uj + 192))[iq];
            float4 w0 = W4[(iq*4+0)*24 + kt];
            float4 w1 = W4[(iq*4+1)*24 + kt];
            float4 w2 = W4[(iq*4+2)*24 + kt];
            float4 w3 = W4[(iq*4+3)*24 + kt];
            ACCROW(a0, ua)
            ACCROW(a1, ub)
            ACCROW(a2, uc)
        }
        ((float4*)S)[(jt*3+0)*24 + kt] = a0;
        ((float4*)S)[(jt*3+1)*24 + kt] = a1;
        ((float4*)S)[(jt*3+2)*24 + kt] = a2;
        __syncthreads();

        // ---- LSTM gate elementwise (c kept in registers) ----
        #pragma unroll
        for (int r = 0; r < 3; r++) {
            int idx = tid + r*NT; int j = idx/24, h = idx%24;
            float s0 = S[j*96 +      h];
            float s1 = S[j*96 + 24 + h];
            float s2 = S[j*96 + 48 + h];
            float s3 = S[j*96 + 72 + h];
            float co = creg[r];
            float ig = sigm_f(s0 + gwm[     h]*co);
            float fg = sigm_f(s1 + gwm[24 + h]*co);
            float c2 = fg*co + ig*tanh_f(s2);
            float og = sigm_f(s3 + gwm[48 + h]*c2);
            float h2 = og*tanh_f(c2);
            creg[r] = c2;
            U[j*96 + 24 + h] = og;     // X_{t+1} = o_t
            U[j*96 + 72 + h] = h2;
        }
        __syncthreads();

        if (t == WARM - 1) {
            // transition: X <- relu(enc(tgt[n, 0])), h/c carried
            #pragma unroll
            for (int r = 0; r < 3; r++) {
                int idx = tid + r*NT; int j = idx/24, h = idx%24;
                const float* x = tgt + (size_t)n*(TOUT*72) + j*3;
                float v = encB[h] + x[0]*encW[h*3+0] + x[1]*encW[h*3+1] + x[2]*encW[h*3+2];
                U[j*96 + 24 + h] = fmaxf(v, 0.f);
            }
            __syncthreads();
        }
        if (t >= WARM) {
            int td = t - WARM;
            float* dst = g_O + ((size_t)n*TOUT + td)*576;
            #pragma unroll
            for (int r = 0; r < 3; r++) {
                int idx = tid + r*NT;
                dst[idx] = U[(idx/24)*96 + 24 + (idx%24)];   // o, layout j*24+h
            }
            // next mutation of these slots is >=2 syncs away; safe
        }
    }
}

// ---------------- decoder GEMM: out[R=65536][72] = O[R][576] @ decW^T + b ----
// block: 64 rows, 192 threads = 8 rowgroups(8 rows) x 24 colgroups(3 cols)
#define DK 96   // k-chunk
__global__ void __launch_bounds__(NT)
dec_kernel(const float* __restrict__ decW, const float* __restrict__ decB,
           float* __restrict__ out)
{
    extern __shared__ float sm[];
    float* Ot = sm;               // [64][96]
    float* Ws = sm + 64*DK;       // [96][72], k-major

    const int tid  = threadIdx.x;
    const int rowg = tid / 24;    // rows rowg*8 .. +7
    const int colg = tid % 24;    // cols colg*3 .. +2
    const size_t row0 = (size_t)blockIdx.x * 64;

    float acc[8][3];
    #pragma unroll
    for (int rr = 0; rr < 8; rr++)
        #pragma unroll
        for (int cc = 0; cc < 3; cc++) acc[rr][cc] = 0.f;

    for (int kc = 0; kc < 576/DK; kc++) {
        // stage O tile (coalesced float4)
        for (int e = tid; e < 64*DK/4; e += NT) {
            int rr = e / (DK/4), kq = e % (DK/4);
            ((float4*)Ot)[rr*(DK/4) + kq] =
                ((const float4*)(g_O + (row0+rr)*576 + kc*DK))[kq];
        }
        // stage W tile transposed: Ws[k][c] = decW[c][kc*DK + k]
        for (int e = tid; e < 72*DK; e += NT) {
            int c = e / DK, k = e % DK;
            Ws[k*72 + c] = decW[(size_t)c*576 + kc*DK + k];
        }
        __syncthreads();

        #pragma unroll 6
        for (int kq = 0; kq < DK/4; kq++) {
            float w[3][4];
            #pragma unroll
            for (int kk = 0; kk < 4; kk++)
                #pragma unroll
                for (int cc = 0; cc < 3; cc++)
                    w[cc][kk] = Ws[(kq*4+kk)*72 + colg*3 + cc];
            #pragma unroll
            for (int rr = 0; rr < 8; rr++) {
                float4 o = ((const float4*)Ot)[(rowg*8+rr)*(DK/4) + kq];
                #pragma unroll
                for (int cc = 0; cc < 3; cc++)
                    acc[rr][cc] = fmaf(o.x, w[cc][0],
                                  fmaf(o.y, w[cc][1],
                                  fmaf(o.z, w[cc][2],
                                  fmaf(o.w, w[cc][3], acc[rr][cc]))));
            }
        }
        __syncthreads();
    }

    #pragma unroll
    for (int rr = 0; rr < 8; rr++)
        #pragma unroll
        for (int cc = 0; cc < 3; cc++)
            out[(row0 + rowg*8 + rr)*72 + colg*3 + cc] =
                acc[rr][cc] + decB[colg*3 + cc];
}

extern "C" void kernel_launch(void* const* d_in, const int* in_sizes, int n_in,
                              void* d_out, int out_size)
{
    const float* src  = (const float*)d_in[0];
    const float* tgt  = (const float*)d_in[1];
    const float* encW = (const float*)d_in[2];
    const float* encB = (const float*)d_in[3];
    const float* xWl  = (const float*)d_in[4];
    const float* xWr  = (const float*)d_in[5];
    const float* xb   = (const float*)d_in[6];
    const float* hWl  = (const float*)d_in[7];
    const float* hWr  = (const float*)d_in[8];
    const float* hb   = (const float*)d_in[9];
    const float* gw   = (const float*)d_in[10];
    const float* gb   = (const float*)d_in[11];
    const float* decW = (const float*)d_in[12];
    const float* decB = (const float*)d_in[13];
    float* out = (float*)d_out;

    const int smem1 = SM1_FLOATS * 4;          // ~56 KB
    const int smem2 = (64*DK + 72*DK) * 4;     // ~52 KB
    cudaFuncSetAttribute(rec_kernel, cudaFuncAttributeMaxDynamicSharedMemorySize, smem1);
    cudaFuncSetAttribute(dec_kernel, cudaFuncAttributeMaxDynamicSharedMemorySize, smem2);

    rec_kernel<<<NBATCH, NT, smem1>>>(src, tgt, encW, encB,
                                      xWl, xWr, xb, hWl, hWr, hb, gw, gb);
    dec_kernel<<<(NBATCH*TOUT)/64, NT, smem2>>>(decW, decB, out);
}